// round 2
// baseline (speedup 1.0000x reference)
#include <cuda_runtime.h>
#include <cstdint>

#define SEQ 384
#define CIN 512
#define HW  64
#define NH  8
#define HD  64
#define K9  (CIN * 9)        // 4608
#define BP  512              // NH * HW batch-pairs

// Scratch (device globals; no runtime allocation)
__device__ float g_feats[5u * 8u * 64u * SEQ * HD];        // [e][hh][p][n][dd]  (252 MB)
__device__ float g_S[2ull * BP * SEQ * SEQ];               // [v][bp][q][k]; v=0 overwritten w/ combined attn (604 MB)
__device__ float g_c2in[(size_t)SEQ * CIN * HW];           // conv2 input (n, c', sp)  (50 MB)

// ---------------------------------------------------------------------------
// Tiled implicit-GEMM conv (3x3, pad 1, stride 1). Per image n:
//   Out[sp][co] = sum_{kk<4608} Im2col[sp][kk] * W[co][kk]
// Block = 64 spatial x 64 co, BK=16, 256 threads, 4x4 micro-tile.
// FIRST:  in = inp (param), out = g_feats in attention layout.
// !FIRST: in = g_c2in,      out = d_out (param) NCHW.
// ---------------------------------------------------------------------------
template <int CO, bool FIRST>
__global__ __launch_bounds__(256) void conv_kernel(const float* __restrict__ in,
                                                   const float* __restrict__ wgt,
                                                   const float* __restrict__ bias,
                                                   float* __restrict__ out)
{
    __shared__ float As[16][64];   // [k][sp]
    __shared__ float Bs[16][68];   // [k][co_local], padded

    const int n   = blockIdx.y;
    const int co0 = blockIdx.x * 64;
    const int tid = threadIdx.x;
    const int tx  = tid & 15, ty = tid >> 4;

    const float* src = FIRST ? in : (const float*)g_c2in;
    const float* inN = src + (size_t)n * CIN * HW;

    float acc[4][4] = {};

    for (int k0 = 0; k0 < K9; k0 += 16) {
        // A tile (im2col on the fly): l -> (kkl = l/64, sp = l%64)
        #pragma unroll
        for (int l = tid; l < 1024; l += 256) {
            int kkl = l >> 6, sp = l & 63;
            int kk  = k0 + kkl;
            int ci  = kk / 9, r = kk % 9;
            int y   = (sp >> 3) + (r / 3) - 1;
            int x   = (sp & 7)  + (r % 3) - 1;
            float v = 0.f;
            if ((unsigned)y < 8u && (unsigned)x < 8u)
                v = inN[ci * 64 + y * 8 + x];
            As[kkl][sp] = v;
        }
        // B tile: l -> (col = l/16, kkl = l%16); W row-major (co, 4608)
        #pragma unroll
        for (int l = tid; l < 1024; l += 256) {
            int col = l >> 4, kkl = l & 15;
            Bs[kkl][col] = wgt[(size_t)(co0 + col) * K9 + k0 + kkl];
        }
        __syncthreads();
        #pragma unroll
        for (int k = 0; k < 16; k++) {
            float4 a = *(const float4*)&As[k][ty * 4];
            float4 b = *(const float4*)&Bs[k][tx * 4];
            float av[4] = {a.x, a.y, a.z, a.w};
            float bv[4] = {b.x, b.y, b.z, b.w};
            #pragma unroll
            for (int i = 0; i < 4; i++)
                #pragma unroll
                for (int j = 0; j < 4; j++)
                    acc[i][j] += av[i] * bv[j];
        }
        __syncthreads();
    }

    #pragma unroll
    for (int i = 0; i < 4; i++) {
        int sp = ty * 4 + i;
        #pragma unroll
        for (int j = 0; j < 4; j++) {
            int co = co0 + tx * 4 + j;
            float v = acc[i][j] + bias[co];
            if (FIRST) {
                int e  = co >> 9;          // co / 512
                int dd = (co >> 3) & 63;   // (co/8) % 64
                int hh = co & 7;           // co % 8
                g_feats[((size_t)((e * 8 + hh) * 64 + sp) * SEQ + n) * HD + dd] = v;
            } else {
                out[((size_t)n * CO + co) * 64 + sp] = v;
            }
        }
    }
}

// ---------------------------------------------------------------------------
// QK: for each bp (=hh*64+p) and variant v (0=same,1=other):
//   S[v][bp][q][k] = 0.125 * dot(Q_e=2+v[bp][q], K_e=v[bp][k]) + attn_mask[head][q][k]
// ---------------------------------------------------------------------------
__global__ __launch_bounds__(256) void qk_kernel(const float* __restrict__ am)
{
    __shared__ float As[16][68];   // [kk][q_local]
    __shared__ float Bs[16][68];   // [kk][k_local]

    const int bpv  = blockIdx.z;
    const int bp   = bpv >> 1, v = bpv & 1;
    const int head = bp >> 6;
    const int m0   = blockIdx.y * 64;
    const int n0   = blockIdx.x * 64;
    const int tid  = threadIdx.x;
    const int tx   = tid & 15, ty = tid >> 4;

    const size_t chunk = (size_t)8 * 64 * SEQ * HD;   // 12,582,912
    const float* Q = g_feats + (size_t)(2 + v) * chunk + (size_t)bp * SEQ * HD;
    const float* K = g_feats + (size_t)v * chunk       + (size_t)bp * SEQ * HD;

    float acc[4][4] = {};

    for (int k0 = 0; k0 < HD; k0 += 16) {
        #pragma unroll
        for (int l = tid; l < 1024; l += 256) {
            int row = l >> 4, kkl = l & 15;
            As[kkl][row] = Q[(size_t)(m0 + row) * HD + k0 + kkl];
            Bs[kkl][row] = K[(size_t)(n0 + row) * HD + k0 + kkl];
        }
        __syncthreads();
        #pragma unroll
        for (int k = 0; k < 16; k++) {
            float4 a = *(const float4*)&As[k][ty * 4];
            float4 b = *(const float4*)&Bs[k][tx * 4];
            float av[4] = {a.x, a.y, a.z, a.w};
            float bv[4] = {b.x, b.y, b.z, b.w};
            #pragma unroll
            for (int i = 0; i < 4; i++)
                #pragma unroll
                for (int j = 0; j < 4; j++)
                    acc[i][j] += av[i] * bv[j];
        }
        __syncthreads();
    }

    float* Sout = g_S + ((size_t)v * BP + bp) * SEQ * SEQ;
    #pragma unroll
    for (int i = 0; i < 4; i++) {
        int q = m0 + ty * 4 + i;
        #pragma unroll
        for (int j = 0; j < 4; j++) {
            int kk = n0 + tx * 4 + j;
            Sout[(size_t)q * SEQ + kk] =
                acc[i][j] * 0.125f + am[((size_t)head * SEQ + q) * SEQ + kk];
        }
    }
}

// ---------------------------------------------------------------------------
// Dual softmax + agent-aware blend, one row per block (128 threads, 3 elems each).
// Overwrites g_S[v=0] row with the combined attention row.
// ---------------------------------------------------------------------------
__global__ __launch_bounds__(128) void softmax_kernel(const int* __restrict__ agent)
{
    __shared__ float red[128];
    const int q = blockIdx.x, bp = blockIdx.y, head = bp >> 6;
    const int t = threadIdx.x;

    const size_t base = ((size_t)bp * SEQ + q) * SEQ;
    float* Ss = g_S + base;
    float* So = g_S + (size_t)BP * SEQ * SEQ + base;
    const int* mrow = agent + ((size_t)head * SEQ + q) * SEQ;

    float s0 = Ss[t], s1 = Ss[t + 128], s2 = Ss[t + 256];
    float o0 = So[t], o1 = So[t + 128], o2 = So[t + 256];

    auto bred = [&](float val, bool ismax) -> float {
        red[t] = val; __syncthreads();
        #pragma unroll
        for (int w = 64; w > 0; w >>= 1) {
            if (t < w) red[t] = ismax ? fmaxf(red[t], red[t + w]) : (red[t] + red[t + w]);
            __syncthreads();
        }
        float r = red[0]; __syncthreads();
        return r;
    };

    float Ms = bred(fmaxf(s0, fmaxf(s1, s2)), true);
    float Mo = bred(fmaxf(o0, fmaxf(o1, o2)), true);

    s0 = __expf(s0 - Ms); s1 = __expf(s1 - Ms); s2 = __expf(s2 - Ms);
    o0 = __expf(o0 - Mo); o1 = __expf(o1 - Mo); o2 = __expf(o2 - Mo);

    float Zs = bred(s0 + s1 + s2, false);
    float Zo = bred(o0 + o1 + o2, false);
    float rs = 1.f / Zs, ro = 1.f / Zo;

    float m0 = (float)mrow[t], m1 = (float)mrow[t + 128], m2 = (float)mrow[t + 256];
    Ss[t]       = m0 * s0 * rs + (1.f - m0) * o0 * ro;
    Ss[t + 128] = m1 * s1 * rs + (1.f - m1) * o1 * ro;
    Ss[t + 256] = m2 * s2 * rs + (1.f - m2) * o2 * ro;
}

// ---------------------------------------------------------------------------
// AV: O[bp][q][dd] = sum_k A[bp][q][k] * V[bp][k][dd], scattered into conv2
// input layout g_c2in[n=q][c'=dd*8+hh][sp=p].
// ---------------------------------------------------------------------------
__global__ __launch_bounds__(256) void av_kernel()
{
    __shared__ float As[16][68];   // [kk][q_local]
    __shared__ float Bs[16][64];   // [kk][dd]

    const int bp = blockIdx.z;
    const int hh = bp >> 6, p = bp & 63;
    const int m0 = blockIdx.y * 64;
    const int tid = threadIdx.x;
    const int tx = tid & 15, ty = tid >> 4;

    const float* A = g_S + (size_t)bp * SEQ * SEQ;
    const float* V = g_feats + (size_t)4 * 8 * 64 * SEQ * HD + (size_t)bp * SEQ * HD;

    float acc[4][4] = {};

    for (int k0 = 0; k0 < SEQ; k0 += 16) {
        #pragma unroll
        for (int l = tid; l < 1024; l += 256) {
            int row = l >> 4, kkl = l & 15;
            As[kkl][row] = A[(size_t)(m0 + row) * SEQ + k0 + kkl];
        }
        #pragma unroll
        for (int l = tid; l < 1024; l += 256) {
            int kkl = l >> 6, dd = l & 63;
            Bs[kkl][dd] = V[(size_t)(k0 + kkl) * HD + dd];
        }
        __syncthreads();
        #pragma unroll
        for (int k = 0; k < 16; k++) {
            float4 a = *(const float4*)&As[k][ty * 4];
            float4 b = *(const float4*)&Bs[k][tx * 4];
            float av[4] = {a.x, a.y, a.z, a.w};
            float bv[4] = {b.x, b.y, b.z, b.w};
            #pragma unroll
            for (int i = 0; i < 4; i++)
                #pragma unroll
                for (int j = 0; j < 4; j++)
                    acc[i][j] += av[i] * bv[j];
        }
        __syncthreads();
    }

    #pragma unroll
    for (int i = 0; i < 4; i++) {
        int q = m0 + ty * 4 + i;
        #pragma unroll
        for (int j = 0; j < 4; j++) {
            int dd = tx * 4 + j;
            g_c2in[((size_t)q * CIN + (dd * 8 + hh)) * 64 + p] = acc[i][j];
        }
    }
}

// ---------------------------------------------------------------------------
extern "C" void kernel_launch(void* const* d_in, const int* in_sizes, int n_in,
                              void* d_out, int out_size)
{
    const float* inp       = (const float*)d_in[0];
    const float* attn_mask = (const float*)d_in[1];
    const int*   agent     = (const int*)  d_in[2];
    const float* w_in      = (const float*)d_in[3];
    const float* b_in      = (const float*)d_in[4];
    const float* w_out     = (const float*)d_in[5];
    const float* b_out     = (const float*)d_in[6];
    float*       out       = (float*)d_out;

    // conv_in: 384 images x (64 spatial x 2560 co), K=4608
    conv_kernel<2560, true><<<dim3(40, 384), 256>>>(inp, w_in, b_in, nullptr);

    // Scores: 512 bp x 2 variants, 384x384, K=64
    qk_kernel<<<dim3(6, 6, 1024), 256>>>(attn_mask);

    // Dual softmax + agent blend (one row per block)
    softmax_kernel<<<dim3(SEQ, BP), 128>>>(agent);

    // attn @ V, scattered to conv2 input layout
    av_kernel<<<dim3(1, 6, BP), 256>>>();

    // conv_out: 384 images x (64 spatial x 512 co), K=4608
    conv_kernel<512, false><<<dim3(8, 384), 256>>>(nullptr, w_out, b_out, out);
}

// round 3
// speedup vs baseline: 1.5834x; 1.5834x over previous
#include <cuda_runtime.h>
#include <cstdint>

#define SEQ 384
#define CIN 512
#define HW  64
#define NH  8
#define HD  64
#define K9  (CIN * 9)        // 4608
#define BP  512              // NH * HW batch-pairs

// Scratch (device globals; no runtime allocation)
__device__ float g_feats[5u * 8u * 64u * SEQ * HD];        // [e][hh][p][n][dd]
__device__ float g_S[2ull * BP * SEQ * SEQ];               // [v][bp][q][k]
__device__ float g_c2in[(size_t)SEQ * CIN * HW];           // conv2 input (n, c', sp)

// ---------------------------------------------------------------------------
// tf32 helpers
// ---------------------------------------------------------------------------
__device__ __forceinline__ void split_tf32(float x, uint32_t& hi, uint32_t& lo)
{
    uint32_t h;
    asm("cvt.rna.tf32.f32 %0, %1;" : "=r"(h) : "f"(x));
    float fl = x - __uint_as_float(h);
    uint32_t l;
    asm("cvt.rna.tf32.f32 %0, %1;" : "=r"(l) : "f"(fl));
    hi = h; lo = l;
}

__device__ __forceinline__ void mma_tf32(float c[4],
                                         uint32_t a0, uint32_t a1, uint32_t a2, uint32_t a3,
                                         uint32_t b0, uint32_t b1)
{
    asm volatile(
        "mma.sync.aligned.m16n8k8.row.col.f32.tf32.tf32.f32 "
        "{%0,%1,%2,%3}, {%4,%5,%6,%7}, {%8,%9}, {%0,%1,%2,%3};"
        : "+f"(c[0]), "+f"(c[1]), "+f"(c[2]), "+f"(c[3])
        : "r"(a0), "r"(a1), "r"(a2), "r"(a3), "r"(b0), "r"(b1));
}

// ---------------------------------------------------------------------------
// 3xTF32 implicit-GEMM conv (3x3, pad 1). CTA tile: M=128 (2 images x 64 sp),
// N=128 (co), BK=32. 8 warps, warp tile 32x64. hi/lo split done at smem fill.
// FIRST:  in = inp param, out -> g_feats (attention layout)
// !FIRST: in = g_c2in,    out -> d_out (NCHW)
// ---------------------------------------------------------------------------
#define LDA 36   // 32 + 4 pad: (4*row + k) mod 32 hits all banks -> conflict-free
#define SMEM_CONV (4 * 128 * LDA * 4)   // Ah, Al, Bh, Bl

template <int CO, bool FIRST>
__global__ void __launch_bounds__(256, 2)
conv_mma_kernel(const float* __restrict__ in,
                const float* __restrict__ wgt,
                const float* __restrict__ bias,
                float* __restrict__ out)
{
    extern __shared__ uint32_t sm[];
    uint32_t* Ah = sm;
    uint32_t* Al = Ah + 128 * LDA;
    uint32_t* Bh = Al + 128 * LDA;
    uint32_t* Bl = Bh + 128 * LDA;

    const int n0   = blockIdx.y * 2;      // first image of pair
    const int co0  = blockIdx.x * 128;
    const int tid  = threadIdx.x;
    const int lane = tid & 31;
    const int wid  = tid >> 5;
    const int rbase = (wid >> 1) * 32;    // warp M origin
    const int cbase = (wid & 1) * 64;     // warp N origin
    const int lg   = lane >> 2;           // group id 0..7
    const int lt   = lane & 3;            // thread-in-group 0..3

    const float* src = FIRST ? in : (const float*)g_c2in;

    float acc[2][8][4] = {};

    for (int k0 = 0; k0 < K9; k0 += 32) {
        // ---- A tile fill (im2col on the fly) + split: 128 rows x 32 k ----
        #pragma unroll
        for (int i = 0; i < 16; i++) {
            int l   = i * 256 + tid;
            int k   = l >> 7;             // 0..31
            int row = l & 127;
            int img = row >> 6, sp = row & 63;
            int kk  = k0 + k;
            int ci  = kk / 9, r = kk % 9;
            int y   = (sp >> 3) + (r / 3) - 1;
            int x   = (sp & 7)  + (r % 3) - 1;
            float v = 0.f;
            if ((unsigned)y < 8u && (unsigned)x < 8u)
                v = src[((size_t)(n0 + img) * CIN + ci) * 64 + y * 8 + x];
            uint32_t hi, lo;
            split_tf32(v, hi, lo);
            Ah[row * LDA + k] = hi;
            Al[row * LDA + k] = lo;
        }
        // ---- B tile fill + split: 128 co x 32 k (float4 along k) ----
        #pragma unroll
        for (int i = 0; i < 4; i++) {
            int l  = i * 256 + tid;
            int co = l >> 3;              // 0..127
            int q  = l & 7;               // float4 index 0..7
            float4 w4 = *(const float4*)&wgt[(size_t)(co0 + co) * K9 + k0 + q * 4];
            float wv[4] = {w4.x, w4.y, w4.z, w4.w};
            #pragma unroll
            for (int j = 0; j < 4; j++) {
                uint32_t hi, lo;
                split_tf32(wv[j], hi, lo);
                Bh[co * LDA + q * 4 + j] = hi;
                Bl[co * LDA + q * 4 + j] = lo;
            }
        }
        __syncthreads();

        // ---- mainloop: 4 k8 steps ----
        #pragma unroll
        for (int k8 = 0; k8 < 4; k8++) {
            int kc = k8 * 8 + lt;
            uint32_t ah[2][4], al[2][4];
            #pragma unroll
            for (int mt = 0; mt < 2; mt++) {
                int r0 = rbase + mt * 16 + lg;
                ah[mt][0] = Ah[r0 * LDA + kc];
                ah[mt][1] = Ah[(r0 + 8) * LDA + kc];
                ah[mt][2] = Ah[r0 * LDA + kc + 4];
                ah[mt][3] = Ah[(r0 + 8) * LDA + kc + 4];
                al[mt][0] = Al[r0 * LDA + kc];
                al[mt][1] = Al[(r0 + 8) * LDA + kc];
                al[mt][2] = Al[r0 * LDA + kc + 4];
                al[mt][3] = Al[(r0 + 8) * LDA + kc + 4];
            }
            #pragma unroll
            for (int nt = 0; nt < 8; nt++) {
                int cc = cbase + nt * 8 + lg;
                uint32_t bh0 = Bh[cc * LDA + kc], bh1 = Bh[cc * LDA + kc + 4];
                uint32_t bl0 = Bl[cc * LDA + kc], bl1 = Bl[cc * LDA + kc + 4];
                #pragma unroll
                for (int mt = 0; mt < 2; mt++) {
                    mma_tf32(acc[mt][nt], ah[mt][0], ah[mt][1], ah[mt][2], ah[mt][3], bh0, bh1);
                    mma_tf32(acc[mt][nt], ah[mt][0], ah[mt][1], ah[mt][2], ah[mt][3], bl0, bl1);
                    mma_tf32(acc[mt][nt], al[mt][0], al[mt][1], al[mt][2], al[mt][3], bh0, bh1);
                }
            }
        }
        __syncthreads();
    }

    // ---- epilogue ----
    #pragma unroll
    for (int mt = 0; mt < 2; mt++) {
        #pragma unroll
        for (int nt = 0; nt < 8; nt++) {
            #pragma unroll
            for (int cp = 0; cp < 4; cp++) {
                int row = rbase + mt * 16 + lg + ((cp >= 2) ? 8 : 0);
                int col = cbase + nt * 8 + lt * 2 + (cp & 1);
                int co  = co0 + col;
                float v = acc[mt][nt][cp] + bias[co];
                int n = n0 + (row >> 6), sp = row & 63;
                if (FIRST) {
                    int e  = co >> 9;
                    int dd = (co >> 3) & 63;
                    int hh = co & 7;
                    g_feats[((size_t)((e * 8 + hh) * 64 + sp) * SEQ + n) * HD + dd] = v;
                } else {
                    out[((size_t)n * CO + co) * 64 + sp] = v;
                }
            }
        }
    }
}

// ---------------------------------------------------------------------------
// QK: S[v][bp][q][k] = 0.125 * dot(Q_{2+v}, K_v) + attn_mask[head][q][k]
// ---------------------------------------------------------------------------
__global__ __launch_bounds__(256) void qk_kernel(const float* __restrict__ am)
{
    __shared__ float As[16][68];
    __shared__ float Bs[16][68];

    const int bpv  = blockIdx.z;
    const int bp   = bpv >> 1, v = bpv & 1;
    const int head = bp >> 6;
    const int m0   = blockIdx.y * 64;
    const int n0   = blockIdx.x * 64;
    const int tid  = threadIdx.x;
    const int tx   = tid & 15, ty = tid >> 4;

    const size_t chunk = (size_t)8 * 64 * SEQ * HD;
    const float* Q = g_feats + (size_t)(2 + v) * chunk + (size_t)bp * SEQ * HD;
    const float* K = g_feats + (size_t)v * chunk       + (size_t)bp * SEQ * HD;

    float acc[4][4] = {};

    for (int k0 = 0; k0 < HD; k0 += 16) {
        #pragma unroll
        for (int l = tid; l < 1024; l += 256) {
            int row = l >> 4, kkl = l & 15;
            As[kkl][row] = Q[(size_t)(m0 + row) * HD + k0 + kkl];
            Bs[kkl][row] = K[(size_t)(n0 + row) * HD + k0 + kkl];
        }
        __syncthreads();
        #pragma unroll
        for (int k = 0; k < 16; k++) {
            float4 a = *(const float4*)&As[k][ty * 4];
            float4 b = *(const float4*)&Bs[k][tx * 4];
            float av[4] = {a.x, a.y, a.z, a.w};
            float bv[4] = {b.x, b.y, b.z, b.w};
            #pragma unroll
            for (int i = 0; i < 4; i++)
                #pragma unroll
                for (int j = 0; j < 4; j++)
                    acc[i][j] += av[i] * bv[j];
        }
        __syncthreads();
    }

    float* Sout = g_S + ((size_t)v * BP + bp) * SEQ * SEQ;
    #pragma unroll
    for (int i = 0; i < 4; i++) {
        int q = m0 + ty * 4 + i;
        #pragma unroll
        for (int j = 0; j < 4; j++) {
            int kk = n0 + tx * 4 + j;
            Sout[(size_t)q * SEQ + kk] =
                acc[i][j] * 0.125f + am[((size_t)head * SEQ + q) * SEQ + kk];
        }
    }
}

// ---------------------------------------------------------------------------
// Dual softmax + agent-aware blend (one row per block)
// ---------------------------------------------------------------------------
__global__ __launch_bounds__(128) void softmax_kernel(const int* __restrict__ agent)
{
    __shared__ float red[128];
    const int q = blockIdx.x, bp = blockIdx.y, head = bp >> 6;
    const int t = threadIdx.x;

    const size_t base = ((size_t)bp * SEQ + q) * SEQ;
    float* Ss = g_S + base;
    float* So = g_S + (size_t)BP * SEQ * SEQ + base;
    const int* mrow = agent + ((size_t)head * SEQ + q) * SEQ;

    float s0 = Ss[t], s1 = Ss[t + 128], s2 = Ss[t + 256];
    float o0 = So[t], o1 = So[t + 128], o2 = So[t + 256];

    auto bred = [&](float val, bool ismax) -> float {
        red[t] = val; __syncthreads();
        #pragma unroll
        for (int w = 64; w > 0; w >>= 1) {
            if (t < w) red[t] = ismax ? fmaxf(red[t], red[t + w]) : (red[t] + red[t + w]);
            __syncthreads();
        }
        float r = red[0]; __syncthreads();
        return r;
    };

    float Ms = bred(fmaxf(s0, fmaxf(s1, s2)), true);
    float Mo = bred(fmaxf(o0, fmaxf(o1, o2)), true);

    s0 = __expf(s0 - Ms); s1 = __expf(s1 - Ms); s2 = __expf(s2 - Ms);
    o0 = __expf(o0 - Mo); o1 = __expf(o1 - Mo); o2 = __expf(o2 - Mo);

    float Zs = bred(s0 + s1 + s2, false);
    float Zo = bred(o0 + o1 + o2, false);
    float rs = 1.f / Zs, ro = 1.f / Zo;

    float m0 = (float)mrow[t], m1 = (float)mrow[t + 128], m2 = (float)mrow[t + 256];
    Ss[t]       = m0 * s0 * rs + (1.f - m0) * o0 * ro;
    Ss[t + 128] = m1 * s1 * rs + (1.f - m1) * o1 * ro;
    Ss[t + 256] = m2 * s2 * rs + (1.f - m2) * o2 * ro;
}

// ---------------------------------------------------------------------------
// AV: O[bp][q][dd] = sum_k A[bp][q][k] * V[bp][k][dd] -> g_c2in[n=q][dd*8+hh][p]
// ---------------------------------------------------------------------------
__global__ __launch_bounds__(256) void av_kernel()
{
    __shared__ float As[16][68];
    __shared__ float Bs[16][64];

    const int bp = blockIdx.z;
    const int hh = bp >> 6, p = bp & 63;
    const int m0 = blockIdx.y * 64;
    const int tid = threadIdx.x;
    const int tx = tid & 15, ty = tid >> 4;

    const float* A = g_S + (size_t)bp * SEQ * SEQ;
    const float* V = g_feats + (size_t)4 * 8 * 64 * SEQ * HD + (size_t)bp * SEQ * HD;

    float acc[4][4] = {};

    for (int k0 = 0; k0 < SEQ; k0 += 16) {
        #pragma unroll
        for (int l = tid; l < 1024; l += 256) {
            int row = l >> 4, kkl = l & 15;
            As[kkl][row] = A[(size_t)(m0 + row) * SEQ + k0 + kkl];
        }
        #pragma unroll
        for (int l = tid; l < 1024; l += 256) {
            int kkl = l >> 6, dd = l & 63;
            Bs[kkl][dd] = V[(size_t)(k0 + kkl) * HD + dd];
        }
        __syncthreads();
        #pragma unroll
        for (int k = 0; k < 16; k++) {
            float4 a = *(const float4*)&As[k][ty * 4];
            float4 b = *(const float4*)&Bs[k][tx * 4];
            float av[4] = {a.x, a.y, a.z, a.w};
            float bv[4] = {b.x, b.y, b.z, b.w};
            #pragma unroll
            for (int i = 0; i < 4; i++)
                #pragma unroll
                for (int j = 0; j < 4; j++)
                    acc[i][j] += av[i] * bv[j];
        }
        __syncthreads();
    }

    #pragma unroll
    for (int i = 0; i < 4; i++) {
        int q = m0 + ty * 4 + i;
        #pragma unroll
        for (int j = 0; j < 4; j++) {
            int dd = tx * 4 + j;
            g_c2in[((size_t)q * CIN + (dd * 8 + hh)) * 64 + p] = acc[i][j];
        }
    }
}

// ---------------------------------------------------------------------------
extern "C" void kernel_launch(void* const* d_in, const int* in_sizes, int n_in,
                              void* d_out, int out_size)
{
    const float* inp       = (const float*)d_in[0];
    const float* attn_mask = (const float*)d_in[1];
    const int*   agent     = (const int*)  d_in[2];
    const float* w_in      = (const float*)d_in[3];
    const float* b_in      = (const float*)d_in[4];
    const float* w_out     = (const float*)d_in[5];
    const float* b_out     = (const float*)d_in[6];
    float*       out       = (float*)d_out;

    cudaFuncSetAttribute(conv_mma_kernel<2560, true>,
                         cudaFuncAttributeMaxDynamicSharedMemorySize, SMEM_CONV);
    cudaFuncSetAttribute(conv_mma_kernel<512, false>,
                         cudaFuncAttributeMaxDynamicSharedMemorySize, SMEM_CONV);

    // conv_in: M = 384*64 (pairs of images), N = 2560, K = 4608
    conv_mma_kernel<2560, true><<<dim3(20, 192), 256, SMEM_CONV>>>(inp, w_in, b_in, nullptr);

    // Scores: 512 bp x 2 variants, 384x384, K=64
    qk_kernel<<<dim3(6, 6, 1024), 256>>>(attn_mask);

    // Dual softmax + agent blend
    softmax_kernel<<<dim3(SEQ, BP), 128>>>(agent);

    // attn @ V
    av_kernel<<<dim3(1, 6, BP), 256>>>();

    // conv_out: N = 512, K = 4608
    conv_mma_kernel<512, false><<<dim3(4, 192), 256, SMEM_CONV>>>(nullptr, w_out, b_out, out);
}

// round 5
// speedup vs baseline: 2.7236x; 1.7200x over previous
#include <cuda_runtime.h>
#include <cuda_fp16.h>
#include <cstdint>

#define SEQ 384
#define CIN 512
#define HW  64
#define NH  8
#define HD  64
#define K9  (CIN * 9)        // 4608
#define BP  512              // NH * HW batch-pairs

// Scratch (device globals; no runtime allocation)
__device__ float    g_feats[5u * 8u * 64u * SEQ * HD];      // [e][hh][p][n][dd]
__device__ float    g_S[2ull * BP * SEQ * SEQ];             // [v][bp][q][k]
__device__ uint32_t g_in_hl[(size_t)SEQ * CIN * HW];        // inp as packed half2(hi,lo)
__device__ uint32_t g_c2_hl[(size_t)SEQ * CIN * HW];        // conv2 input, packed half2(hi,lo)
__device__ __half   g_wh_in[(size_t)2560 * K9];             // conv_in weights hi
__device__ __half   g_wl_in[(size_t)2560 * K9];             // conv_in weights lo
__device__ __half   g_wh_out[(size_t)512 * K9];
__device__ __half   g_wl_out[(size_t)512 * K9];

// ---------------------------------------------------------------------------
// helpers
// ---------------------------------------------------------------------------
__device__ __forceinline__ uint32_t split_h2(float x)
{
    __half hi = __float2half_rn(x);
    __half lo = __float2half_rn(x - __half2float(hi));
    return (uint32_t)__half_as_ushort(hi) | ((uint32_t)__half_as_ushort(lo) << 16);
}

__device__ __forceinline__ void mma_f16(float c[4], const uint32_t a[4],
                                        uint32_t b0, uint32_t b1)
{
    asm volatile(
        "mma.sync.aligned.m16n8k16.row.col.f32.f16.f16.f32 "
        "{%0,%1,%2,%3}, {%4,%5,%6,%7}, {%8,%9}, {%0,%1,%2,%3};"
        : "+f"(c[0]), "+f"(c[1]), "+f"(c[2]), "+f"(c[3])
        : "r"(a[0]), "r"(a[1]), "r"(a[2]), "r"(a[3]), "r"(b0), "r"(b1));
}

// ---------------------------------------------------------------------------
// Pre-split kernels (run once per launch; trivial elementwise)
// ---------------------------------------------------------------------------
__global__ void split_inp_kernel(const float* __restrict__ in, int n)
{
    int i = blockIdx.x * 256 + threadIdx.x;
    if (i < n) g_in_hl[i] = split_h2(in[i]);
}

__global__ void split_w_kernel(const float* __restrict__ w,
                               __half* __restrict__ wh, __half* __restrict__ wl, int n)
{
    int i = blockIdx.x * 256 + threadIdx.x;
    if (i < n) {
        float x = w[i];
        __half hi = __float2half_rn(x);
        wh[i] = hi;
        wl[i] = __float2half_rn(x - __half2float(hi));
    }
}

// ---------------------------------------------------------------------------
// fp16x3 implicit-GEMM conv (3x3, pad 1) on mma.sync.m16n8k16.
// CTA: 256 threads, tile M=128 (2 images x 64 sp) x N=128 (co), BK=32.
// 8 warps, warp tile 32x64. smem: Ah/Al/Bh/Bl as u32 (fp16 pairs along k),
// row stride 20 words (40 fp16) -> conflict-free fragment loads.
// A source: packed half2(hi,lo) arrays (g_in_hl or g_c2_hl).
// B source: pre-split fp16 weight arrays.
// ---------------------------------------------------------------------------
#define LDK2 20   // u32 words per row (16 used + 4 pad)

template <int CO, bool FIRST>
__global__ void __launch_bounds__(256, 2)
conv_f16_kernel(const uint32_t* __restrict__ src_hl,
                const __half* __restrict__ gwh,
                const __half* __restrict__ gwl,
                const float* __restrict__ bias,
                float* __restrict__ out)
{
    __shared__ uint32_t Ah[128 * LDK2];
    __shared__ uint32_t Al[128 * LDK2];
    __shared__ uint32_t Bh[128 * LDK2];
    __shared__ uint32_t Bl[128 * LDK2];

    const int n0   = blockIdx.y * 2;
    const int co0  = blockIdx.x * 128;
    const int tid  = threadIdx.x;
    const int lane = tid & 31;
    const int wid  = tid >> 5;
    const int rbase = (wid >> 1) * 32;
    const int cbase = (wid & 1) * 64;
    const int lg   = lane >> 2;
    const int lt   = lane & 3;

    float acc[2][8][4] = {};

    for (int k0 = 0; k0 < K9; k0 += 32) {
        // ---- A fill: 128 rows x 16 k-pairs, im2col gather of packed half2 ----
        #pragma unroll
        for (int i = 0; i < 8; i++) {
            int p   = i * 256 + tid;
            int row = p >> 4;              // 0..127
            int kp  = p & 15;
            int img = row >> 6, sp = row & 63;
            const uint32_t* srcN = src_hl + (size_t)(n0 + img) * CIN * 64;
            uint32_t v[2];
            #pragma unroll
            for (int j = 0; j < 2; j++) {
                int kk = k0 + kp * 2 + j;
                int ci = kk / 9, r = kk % 9;
                int y  = (sp >> 3) + (r / 3) - 1;
                int x  = (sp & 7)  + (r % 3) - 1;
                v[j] = ((unsigned)y < 8u && (unsigned)x < 8u)
                     ? srcN[ci * 64 + y * 8 + x] : 0u;
            }
            Ah[row * LDK2 + kp] = __byte_perm(v[0], v[1], 0x5410);  // (hi0,hi1)
            Al[row * LDK2 + kp] = __byte_perm(v[0], v[1], 0x7632);  // (lo0,lo1)
        }
        // ---- B fill: 128 co x 32 k fp16, LDG.128 + STS.128 ----
        #pragma unroll
        for (int i = 0; i < 2; i++) {
            int cidx = i * 256 + tid;      // 0..511
            int co = cidx >> 2, ch = cidx & 3;
            size_t gofs = (size_t)(co0 + co) * K9 + k0 + ch * 8;
            uint4 h = *(const uint4*)(gwh + gofs);
            uint4 l = *(const uint4*)(gwl + gofs);
            *(uint4*)&Bh[co * LDK2 + ch * 4] = h;
            *(uint4*)&Bl[co * LDK2 + ch * 4] = l;
        }
        __syncthreads();

        // ---- mainloop: 2 k16 steps ----
        #pragma unroll
        for (int k16 = 0; k16 < 2; k16++) {
            int kw = k16 * 8 + lt;
            uint32_t ah[2][4], al[2][4];
            #pragma unroll
            for (int mt = 0; mt < 2; mt++) {
                int r0 = rbase + mt * 16 + lg;
                ah[mt][0] = Ah[r0 * LDK2 + kw];
                ah[mt][1] = Ah[(r0 + 8) * LDK2 + kw];
                ah[mt][2] = Ah[r0 * LDK2 + kw + 4];
                ah[mt][3] = Ah[(r0 + 8) * LDK2 + kw + 4];
                al[mt][0] = Al[r0 * LDK2 + kw];
                al[mt][1] = Al[(r0 + 8) * LDK2 + kw];
                al[mt][2] = Al[r0 * LDK2 + kw + 4];
                al[mt][3] = Al[(r0 + 8) * LDK2 + kw + 4];
            }
            #pragma unroll
            for (int nt = 0; nt < 8; nt++) {
                int cc = cbase + nt * 8 + lg;
                uint32_t bh0 = Bh[cc * LDK2 + kw], bh1 = Bh[cc * LDK2 + kw + 4];
                uint32_t bl0 = Bl[cc * LDK2 + kw], bl1 = Bl[cc * LDK2 + kw + 4];
                #pragma unroll
                for (int mt = 0; mt < 2; mt++) {
                    mma_f16(acc[mt][nt], ah[mt], bh0, bh1);
                    mma_f16(acc[mt][nt], ah[mt], bl0, bl1);
                    mma_f16(acc[mt][nt], al[mt], bh0, bh1);
                }
            }
        }
        __syncthreads();
    }

    // ---- epilogue ----
    #pragma unroll
    for (int mt = 0; mt < 2; mt++) {
        #pragma unroll
        for (int nt = 0; nt < 8; nt++) {
            #pragma unroll
            for (int cp = 0; cp < 4; cp++) {
                int row = rbase + mt * 16 + lg + ((cp >= 2) ? 8 : 0);
                int col = cbase + nt * 8 + lt * 2 + (cp & 1);
                int co  = co0 + col;
                float v = acc[mt][nt][cp] + bias[co];
                int n = n0 + (row >> 6), sp = row & 63;
                if (FIRST) {
                    int e  = co >> 9;
                    int dd = (co >> 3) & 63;
                    int hh = co & 7;
                    g_feats[((size_t)((e * 8 + hh) * 64 + sp) * SEQ + n) * HD + dd] = v;
                } else {
                    out[((size_t)n * CO + co) * 64 + sp] = v;
                }
            }
        }
    }
}

// ---------------------------------------------------------------------------
// QK: S[v][bp][q][k] = 0.125 * dot(Q_{2+v}, K_v) + attn_mask[head][q][k]
// ---------------------------------------------------------------------------
__global__ __launch_bounds__(256) void qk_kernel(const float* __restrict__ am)
{
    __shared__ float As[16][68];
    __shared__ float Bs[16][68];

    const int bpv  = blockIdx.z;
    const int bp   = bpv >> 1, v = bpv & 1;
    const int head = bp >> 6;
    const int m0   = blockIdx.y * 64;
    const int n0   = blockIdx.x * 64;
    const int tid  = threadIdx.x;
    const int tx   = tid & 15, ty = tid >> 4;

    const size_t chunk = (size_t)8 * 64 * SEQ * HD;
    const float* Q = g_feats + (size_t)(2 + v) * chunk + (size_t)bp * SEQ * HD;
    const float* K = g_feats + (size_t)v * chunk       + (size_t)bp * SEQ * HD;

    float acc[4][4] = {};

    for (int k0 = 0; k0 < HD; k0 += 16) {
        #pragma unroll
        for (int l = tid; l < 1024; l += 256) {
            int row = l >> 4, kkl = l & 15;
            As[kkl][row] = Q[(size_t)(m0 + row) * HD + k0 + kkl];
            Bs[kkl][row] = K[(size_t)(n0 + row) * HD + k0 + kkl];
        }
        __syncthreads();
        #pragma unroll
        for (int k = 0; k < 16; k++) {
            float4 a = *(const float4*)&As[k][ty * 4];
            float4 b = *(const float4*)&Bs[k][tx * 4];
            float av[4] = {a.x, a.y, a.z, a.w};
            float bv[4] = {b.x, b.y, b.z, b.w};
            #pragma unroll
            for (int i = 0; i < 4; i++)
                #pragma unroll
                for (int j = 0; j < 4; j++)
                    acc[i][j] += av[i] * bv[j];
        }
        __syncthreads();
    }

    float* Sout = g_S + ((size_t)v * BP + bp) * SEQ * SEQ;
    #pragma unroll
    for (int i = 0; i < 4; i++) {
        int q = m0 + ty * 4 + i;
        #pragma unroll
        for (int j = 0; j < 4; j++) {
            int kk = n0 + tx * 4 + j;
            Sout[(size_t)q * SEQ + kk] =
                acc[i][j] * 0.125f + am[((size_t)head * SEQ + q) * SEQ + kk];
        }
    }
}

// ---------------------------------------------------------------------------
// Dual softmax + agent-aware blend (one row per block)
// ---------------------------------------------------------------------------
__global__ __launch_bounds__(128) void softmax_kernel(const int* __restrict__ agent)
{
    __shared__ float red[128];
    const int q = blockIdx.x, bp = blockIdx.y, head = bp >> 6;
    const int t = threadIdx.x;

    const size_t base = ((size_t)bp * SEQ + q) * SEQ;
    float* Ss = g_S + base;
    float* So = g_S + (size_t)BP * SEQ * SEQ + base;
    const int* mrow = agent + ((size_t)head * SEQ + q) * SEQ;

    float s0 = Ss[t], s1 = Ss[t + 128], s2 = Ss[t + 256];
    float o0 = So[t], o1 = So[t + 128], o2 = So[t + 256];

    auto bred = [&](float val, bool ismax) -> float {
        red[t] = val; __syncthreads();
        #pragma unroll
        for (int w = 64; w > 0; w >>= 1) {
            if (t < w) red[t] = ismax ? fmaxf(red[t], red[t + w]) : (red[t] + red[t + w]);
            __syncthreads();
        }
        float r = red[0]; __syncthreads();
        return r;
    };

    float Ms = bred(fmaxf(s0, fmaxf(s1, s2)), true);
    float Mo = bred(fmaxf(o0, fmaxf(o1, o2)), true);

    s0 = __expf(s0 - Ms); s1 = __expf(s1 - Ms); s2 = __expf(s2 - Ms);
    o0 = __expf(o0 - Mo); o1 = __expf(o1 - Mo); o2 = __expf(o2 - Mo);

    float Zs = bred(s0 + s1 + s2, false);
    float Zo = bred(o0 + o1 + o2, false);
    float rs = 1.f / Zs, ro = 1.f / Zo;

    float m0 = (float)mrow[t], m1 = (float)mrow[t + 128], m2 = (float)mrow[t + 256];
    Ss[t]       = m0 * s0 * rs + (1.f - m0) * o0 * ro;
    Ss[t + 128] = m1 * s1 * rs + (1.f - m1) * o1 * ro;
    Ss[t + 256] = m2 * s2 * rs + (1.f - m2) * o2 * ro;
}

// ---------------------------------------------------------------------------
// AV: O[bp][q][dd] = sum_k A[bp][q][k] * V[bp][k][dd]
// writes packed half2(hi,lo) into g_c2_hl[n=q][c'=dd*8+hh][sp=p]
// ---------------------------------------------------------------------------
__global__ __launch_bounds__(256) void av_kernel()
{
    __shared__ float As[16][68];
    __shared__ float Bs[16][64];

    const int bp = blockIdx.z;
    const int hh = bp >> 6, p = bp & 63;
    const int m0 = blockIdx.y * 64;
    const int tid = threadIdx.x;
    const int tx = tid & 15, ty = tid >> 4;

    const float* A = g_S + (size_t)bp * SEQ * SEQ;
    const float* V = g_feats + (size_t)4 * 8 * 64 * SEQ * HD + (size_t)bp * SEQ * HD;

    float acc[4][4] = {};

    for (int k0 = 0; k0 < SEQ; k0 += 16) {
        #pragma unroll
        for (int l = tid; l < 1024; l += 256) {
            int row = l >> 4, kkl = l & 15;
            As[kkl][row] = A[(size_t)(m0 + row) * SEQ + k0 + kkl];
        }
        #pragma unroll
        for (int l = tid; l < 1024; l += 256) {
            int kkl = l >> 6, dd = l & 63;
            Bs[kkl][dd] = V[(size_t)(k0 + kkl) * HD + dd];
        }
        __syncthreads();
        #pragma unroll
        for (int k = 0; k < 16; k++) {
            float4 a = *(const float4*)&As[k][ty * 4];
            float4 b = *(const float4*)&Bs[k][tx * 4];
            float av[4] = {a.x, a.y, a.z, a.w};
            float bv[4] = {b.x, b.y, b.z, b.w};
            #pragma unroll
            for (int i = 0; i < 4; i++)
                #pragma unroll
                for (int j = 0; j < 4; j++)
                    acc[i][j] += av[i] * bv[j];
        }
        __syncthreads();
    }

    #pragma unroll
    for (int i = 0; i < 4; i++) {
        int q = m0 + ty * 4 + i;
        #pragma unroll
        for (int j = 0; j < 4; j++) {
            int dd = tx * 4 + j;
            g_c2_hl[((size_t)q * CIN + (dd * 8 + hh)) * 64 + p] = split_h2(acc[i][j]);
        }
    }
}

// ---------------------------------------------------------------------------
extern "C" void kernel_launch(void* const* d_in, const int* in_sizes, int n_in,
                              void* d_out, int out_size)
{
    const float* inp       = (const float*)d_in[0];
    const float* attn_mask = (const float*)d_in[1];
    const int*   agent     = (const int*)  d_in[2];
    const float* w_in      = (const float*)d_in[3];
    const float* b_in      = (const float*)d_in[4];
    const float* w_out     = (const float*)d_in[5];
    const float* b_out     = (const float*)d_in[6];
    float*       out       = (float*)d_out;

    uint32_t* in_hl;  cudaGetSymbolAddress((void**)&in_hl,  g_in_hl);
    uint32_t* c2_hl;  cudaGetSymbolAddress((void**)&c2_hl,  g_c2_hl);
    __half *wh_in, *wl_in, *wh_out, *wl_out;
    cudaGetSymbolAddress((void**)&wh_in,  g_wh_in);
    cudaGetSymbolAddress((void**)&wl_in,  g_wl_in);
    cudaGetSymbolAddress((void**)&wh_out, g_wh_out);
    cudaGetSymbolAddress((void**)&wl_out, g_wl_out);

    // Pre-split inputs and weights into fp16 hi/lo (once)
    const int n_inp  = SEQ * CIN * HW;          // 12,582,912
    const int n_win  = 2560 * K9;               // 11,796,480
    const int n_wout = 512 * K9;                //  2,359,296
    split_inp_kernel<<<(n_inp + 255) / 256, 256>>>(inp, n_inp);
    split_w_kernel<<<(n_win + 255) / 256, 256>>>(w_in, wh_in, wl_in, n_win);
    split_w_kernel<<<(n_wout + 255) / 256, 256>>>(w_out, wh_out, wl_out, n_wout);

    // conv_in: M = 384*64 (2 images/CTA -> 192), N = 2560 (20 tiles), K = 4608
    conv_f16_kernel<2560, true><<<dim3(20, 192), 256>>>(in_hl, wh_in, wl_in, b_in, nullptr);

    // Scores: 512 bp x 2 variants, 384x384, K=64
    qk_kernel<<<dim3(6, 6, 1024), 256>>>(attn_mask);

    // Dual softmax + agent blend
    softmax_kernel<<<dim3(SEQ, BP), 128>>>(agent);

    // attn @ V -> packed half2 conv2 input
    av_kernel<<<dim3(1, 6, BP), 256>>>();

    // conv_out: N = 512 (4 tiles), K = 4608
    conv_f16_kernel<512, false><<<dim3(4, 192), 256>>>(c2_hl, wh_out, wl_out, b_out, out);
}

// round 6
// speedup vs baseline: 3.2712x; 1.2011x over previous
#include <cuda_runtime.h>
#include <cuda_fp16.h>
#include <cstdint>

#define SEQ 384
#define CIN 512
#define HW  64
#define NH  8
#define HD  64
#define K9  (CIN * 9)        // 4608
#define BP  512              // NH * HW batch-pairs
#define NROWS (SEQ * HW)     // 24576 GEMM rows

// Scratch (device globals; no runtime allocation)
__device__ float    g_feats[5u * 8u * 64u * SEQ * HD];      // [e][hh][p][n][dd]
__device__ float    g_S[2ull * BP * SEQ * SEQ];             // [v][bp][q][k]
__device__ uint32_t g_c2_hl[(size_t)SEQ * CIN * HW];        // conv2 input, packed half2(hi,lo)
__device__ __half   g_Ah[(size_t)NROWS * K9];               // im2col hi plane (k' = r*512+ci)
__device__ __half   g_Al[(size_t)NROWS * K9];               // im2col lo plane
__device__ __half   g_wh_in[(size_t)2560 * K9];             // weights hi, k'-order
__device__ __half   g_wl_in[(size_t)2560 * K9];
__device__ __half   g_wh_out[(size_t)512 * K9];
__device__ __half   g_wl_out[(size_t)512 * K9];

// ---------------------------------------------------------------------------
// helpers
// ---------------------------------------------------------------------------
__device__ __forceinline__ uint32_t split_h2(float x)
{
    __half hi = __float2half_rn(x);
    __half lo = __float2half_rn(x - __half2float(hi));
    return (uint32_t)__half_as_ushort(hi) | ((uint32_t)__half_as_ushort(lo) << 16);
}

__device__ __forceinline__ void mma_f16(float c[4], const uint32_t a[4],
                                        uint32_t b0, uint32_t b1)
{
    asm volatile(
        "mma.sync.aligned.m16n8k16.row.col.f32.f16.f16.f32 "
        "{%0,%1,%2,%3}, {%4,%5,%6,%7}, {%8,%9}, {%0,%1,%2,%3};"
        : "+f"(c[0]), "+f"(c[1]), "+f"(c[2]), "+f"(c[3])
        : "r"(a[0]), "r"(a[1]), "r"(a[2]), "r"(a[3]), "r"(b0), "r"(b1));
}
__device__ __forceinline__ void ldsm4(uint32_t& r0, uint32_t& r1, uint32_t& r2,
                                      uint32_t& r3, uint32_t addr)
{
    asm volatile("ldmatrix.sync.aligned.m8n8.x4.shared.b16 {%0,%1,%2,%3}, [%4];"
                 : "=r"(r0), "=r"(r1), "=r"(r2), "=r"(r3) : "r"(addr));
}
__device__ __forceinline__ void cpa16(uint32_t dst, const void* src)
{
    asm volatile("cp.async.cg.shared.global [%0], [%1], 16;" :: "r"(dst), "l"(src));
}

// ---------------------------------------------------------------------------
// Weight split + permute to k' = r*512 + ci order (output-indexed, coalesced writes)
// ---------------------------------------------------------------------------
__global__ void split_w_kernel(const float* __restrict__ w,
                               __half* __restrict__ wh, __half* __restrict__ wl, int n)
{
    int i = blockIdx.x * 256 + threadIdx.x;
    if (i >= n) return;
    int co = i / K9;
    int kn = i - co * K9;
    int r = kn >> 9, ci = kn & 511;
    float x = w[(size_t)co * K9 + ci * 9 + r];
    __half hi = __float2half_rn(x);
    wh[i] = hi;
    wl[i] = __float2half_rn(x - __half2float(hi));
}

// ---------------------------------------------------------------------------
// im2col expansion into hi/lo fp16 planes, k' = r*512 + ci.
// Block = (n, 64-channel chunk). Loads [64ci x 64sp] coalesced, splits into
// smem transposed tiles [sp][ci], then writes 9 shifted copies coalesced.
// PACKED: src = g_c2_hl (already split, packed); else raw float input.
// ---------------------------------------------------------------------------
template <bool PACKED>
__global__ __launch_bounds__(256) void im2col_kernel(const float* __restrict__ srcF)
{
    __shared__ ushort th[64][72];
    __shared__ ushort tl[64][72];
    const int n   = blockIdx.x;
    const int ci0 = blockIdx.y * 64;
    const int t   = threadIdx.x;

    {
        int sp4 = (t & 15) * 4;
        int ciL = t >> 4;
        #pragma unroll
        for (int pass = 0; pass < 4; pass++) {
            int ci = pass * 16 + ciL;
            if (PACKED) {
                uint4 w = *(const uint4*)(g_c2_hl + ((size_t)n * CIN + ci0 + ci) * 64 + sp4);
                uint32_t ws[4] = {w.x, w.y, w.z, w.w};
                #pragma unroll
                for (int j = 0; j < 4; j++) {
                    th[sp4 + j][ci] = (ushort)(ws[j] & 0xFFFF);
                    tl[sp4 + j][ci] = (ushort)(ws[j] >> 16);
                }
            } else {
                float4 v = *(const float4*)(srcF + ((size_t)n * CIN + ci0 + ci) * 64 + sp4);
                float vs[4] = {v.x, v.y, v.z, v.w};
                #pragma unroll
                for (int j = 0; j < 4; j++) {
                    __half hi = __float2half_rn(vs[j]);
                    __half lo = __float2half_rn(vs[j] - __half2float(hi));
                    th[sp4 + j][ci] = __half_as_ushort(hi);
                    tl[sp4 + j][ci] = __half_as_ushort(lo);
                }
            }
        }
    }
    __syncthreads();

    const int ciQ = t & 15;            // 4 channels per thread
    const int rg  = t >> 4;            // 16 sp-row groups
    #pragma unroll
    for (int si = 0; si < 4; si++) {
        int sp = si * 16 + rg;
        int yy = sp >> 3, xx = sp & 7;
        size_t obase = (size_t)(n * 64 + sp) * K9 + ci0 + ciQ * 4;
        #pragma unroll
        for (int r = 0; r < 9; r++) {
            int y = yy + r / 3 - 1, x = xx + r % 3 - 1;
            uint2 vh = make_uint2(0, 0), vl = make_uint2(0, 0);
            if ((unsigned)y < 8u && (unsigned)x < 8u) {
                int spp = y * 8 + x;
                vh = *(const uint2*)&th[spp][ciQ * 4];
                vl = *(const uint2*)&tl[spp][ciQ * 4];
            }
            *(uint2*)&g_Ah[obase + (size_t)r * 512] = vh;
            *(uint2*)&g_Al[obase + (size_t)r * 512] = vl;
        }
    }
}

// ---------------------------------------------------------------------------
// fp16x3 GEMM conv on mma.sync.m16n8k16 + ldmatrix + cp.async double buffer.
// CTA 256 thr, tile M=128 x N=128 x BK=32. 8 warps, warp tile 32x64.
// smem stage (40KB): [Ah][Al][Bh][Bl], each 128 rows x 20 u32 (16 used + 4 pad).
// ---------------------------------------------------------------------------
#define LDK2 20
#define STG_BYTES (4 * 128 * LDK2 * 4)   // 40960
#define SMEM_BYTES (2 * STG_BYTES)       // 81920

__device__ __forceinline__ void conv_fill(uint32_t base, int row0, int co0, int k0,
                                          int tid, const __half* gwh, const __half* gwl)
{
    #pragma unroll
    for (int h = 0; h < 2; h++) {
        int c = h * 256 + tid;
        int row = c >> 2, q = c & 3;
        uint32_t doff = (uint32_t)((row * LDK2 + q * 4) * 4);
        size_t aoff = (size_t)(row0 + row) * K9 + k0 + q * 8;
        size_t boff = (size_t)(co0 + row) * K9 + k0 + q * 8;
        cpa16(base + doff,         g_Ah + aoff);
        cpa16(base + 10240 + doff, g_Al + aoff);
        cpa16(base + 20480 + doff, gwh + boff);
        cpa16(base + 30720 + doff, gwl + boff);
    }
    asm volatile("cp.async.commit_group;" ::: "memory");
}

template <int CO, bool FIRST>
__global__ void __launch_bounds__(256, 2)
conv_f16_kernel(const __half* __restrict__ gwh,
                const __half* __restrict__ gwl,
                const float* __restrict__ bias,
                float* __restrict__ out)
{
    extern __shared__ uint32_t sm[];
    const uint32_t smb = (uint32_t)__cvta_generic_to_shared(sm);

    const int row0 = blockIdx.y * 128;
    const int co0  = blockIdx.x * 128;
    const int tid  = threadIdx.x;
    const int lane = tid & 31, wid = tid >> 5;
    const int rbase = (wid >> 1) * 32;
    const int cbase = (wid & 1) * 64;
    const int lg = lane >> 2, lt = lane & 3;

    // ldmatrix lane addressing (word offsets within array)
    const int aRow = lane & 15, aCol = (lane >> 4) * 4;
    const int bRow = ((lane >> 4) & 1) * 8 + (lane & 7);
    const int bCol = ((lane >> 3) & 1) * 4;

    float acc[2][8][4] = {};

    conv_fill(smb, row0, co0, 0, tid, gwh, gwl);

    const int NITER = K9 / 32;    // 144
    for (int it = 0; it < NITER; it++) {
        const int s = it & 1;
        asm volatile("cp.async.wait_group 0;" ::: "memory");
        __syncthreads();
        if (it + 1 < NITER)
            conv_fill(smb + (1 - s) * STG_BYTES, row0, co0, (it + 1) * 32, tid, gwh, gwl);

        const uint32_t base = smb + s * STG_BYTES;
        #pragma unroll
        for (int k16 = 0; k16 < 2; k16++) {
            const uint32_t ko = k16 * 8;
            uint32_t ah[2][4], al[2][4];
            #pragma unroll
            for (int mt = 0; mt < 2; mt++) {
                uint32_t aw = base + ((rbase + mt * 16 + aRow) * LDK2 + aCol + ko) * 4;
                ldsm4(ah[mt][0], ah[mt][1], ah[mt][2], ah[mt][3], aw);
                ldsm4(al[mt][0], al[mt][1], al[mt][2], al[mt][3], aw + 10240);
            }
            #pragma unroll
            for (int pr = 0; pr < 4; pr++) {
                uint32_t bw = base + 20480 +
                              ((cbase + pr * 16 + bRow) * LDK2 + bCol + ko) * 4;
                uint32_t bh0, bh1, bh2, bh3, bl0, bl1, bl2, bl3;
                ldsm4(bh0, bh1, bh2, bh3, bw);
                ldsm4(bl0, bl1, bl2, bl3, bw + 10240);
                #pragma unroll
                for (int mt = 0; mt < 2; mt++) {
                    mma_f16(acc[mt][2 * pr],     ah[mt], bh0, bh1);
                    mma_f16(acc[mt][2 * pr],     ah[mt], bl0, bl1);
                    mma_f16(acc[mt][2 * pr],     al[mt], bh0, bh1);
                    mma_f16(acc[mt][2 * pr + 1], ah[mt], bh2, bh3);
                    mma_f16(acc[mt][2 * pr + 1], ah[mt], bl2, bl3);
                    mma_f16(acc[mt][2 * pr + 1], al[mt], bh2, bh3);
                }
            }
        }
        __syncthreads();
    }

    // ---- epilogue ----
    #pragma unroll
    for (int mt = 0; mt < 2; mt++) {
        #pragma unroll
        for (int nt = 0; nt < 8; nt++) {
            #pragma unroll
            for (int cp = 0; cp < 4; cp++) {
                int row = row0 + rbase + mt * 16 + lg + ((cp >= 2) ? 8 : 0);
                int col = cbase + nt * 8 + lt * 2 + (cp & 1);
                int co  = co0 + col;
                float v = acc[mt][nt][cp] + bias[co];
                int n = row >> 6, sp = row & 63;
                if (FIRST) {
                    int e  = co >> 9;
                    int dd = (co >> 3) & 63;
                    int hh = co & 7;
                    g_feats[((size_t)((e * 8 + hh) * 64 + sp) * SEQ + n) * HD + dd] = v;
                } else {
                    out[((size_t)n * CO + co) * 64 + sp] = v;
                }
            }
        }
    }
}

// ---------------------------------------------------------------------------
// QK: S[v][bp][q][k] = 0.125 * dot(Q_{2+v}, K_v) + attn_mask[head][q][k]
// ---------------------------------------------------------------------------
__global__ __launch_bounds__(256) void qk_kernel(const float* __restrict__ am)
{
    __shared__ float As[16][68];
    __shared__ float Bs[16][68];

    const int bpv  = blockIdx.z;
    const int bp   = bpv >> 1, v = bpv & 1;
    const int head = bp >> 6;
    const int m0   = blockIdx.y * 64;
    const int n0   = blockIdx.x * 64;
    const int tid  = threadIdx.x;
    const int tx   = tid & 15, ty = tid >> 4;

    const size_t chunk = (size_t)8 * 64 * SEQ * HD;
    const float* Q = g_feats + (size_t)(2 + v) * chunk + (size_t)bp * SEQ * HD;
    const float* K = g_feats + (size_t)v * chunk       + (size_t)bp * SEQ * HD;

    float acc[4][4] = {};

    for (int k0 = 0; k0 < HD; k0 += 16) {
        #pragma unroll
        for (int l = tid; l < 1024; l += 256) {
            int row = l >> 4, kkl = l & 15;
            As[kkl][row] = Q[(size_t)(m0 + row) * HD + k0 + kkl];
            Bs[kkl][row] = K[(size_t)(n0 + row) * HD + k0 + kkl];
        }
        __syncthreads();
        #pragma unroll
        for (int k = 0; k < 16; k++) {
            float4 a = *(const float4*)&As[k][ty * 4];
            float4 b = *(const float4*)&Bs[k][tx * 4];
            float av[4] = {a.x, a.y, a.z, a.w};
            float bv[4] = {b.x, b.y, b.z, b.w};
            #pragma unroll
            for (int i = 0; i < 4; i++)
                #pragma unroll
                for (int j = 0; j < 4; j++)
                    acc[i][j] += av[i] * bv[j];
        }
        __syncthreads();
    }

    float* Sout = g_S + ((size_t)v * BP + bp) * SEQ * SEQ;
    #pragma unroll
    for (int i = 0; i < 4; i++) {
        int q = m0 + ty * 4 + i;
        #pragma unroll
        for (int j = 0; j < 4; j++) {
            int kk = n0 + tx * 4 + j;
            Sout[(size_t)q * SEQ + kk] =
                acc[i][j] * 0.125f + am[((size_t)head * SEQ + q) * SEQ + kk];
        }
    }
}

// ---------------------------------------------------------------------------
// Dual softmax + agent-aware blend (one row per block)
// ---------------------------------------------------------------------------
__global__ __launch_bounds__(128) void softmax_kernel(const int* __restrict__ agent)
{
    __shared__ float red[128];
    const int q = blockIdx.x, bp = blockIdx.y, head = bp >> 6;
    const int t = threadIdx.x;

    const size_t base = ((size_t)bp * SEQ + q) * SEQ;
    float* Ss = g_S + base;
    float* So = g_S + (size_t)BP * SEQ * SEQ + base;
    const int* mrow = agent + ((size_t)head * SEQ + q) * SEQ;

    float s0 = Ss[t], s1 = Ss[t + 128], s2 = Ss[t + 256];
    float o0 = So[t], o1 = So[t + 128], o2 = So[t + 256];

    auto bred = [&](float val, bool ismax) -> float {
        red[t] = val; __syncthreads();
        #pragma unroll
        for (int w = 64; w > 0; w >>= 1) {
            if (t < w) red[t] = ismax ? fmaxf(red[t], red[t + w]) : (red[t] + red[t + w]);
            __syncthreads();
        }
        float r = red[0]; __syncthreads();
        return r;
    };

    float Ms = bred(fmaxf(s0, fmaxf(s1, s2)), true);
    float Mo = bred(fmaxf(o0, fmaxf(o1, o2)), true);

    s0 = __expf(s0 - Ms); s1 = __expf(s1 - Ms); s2 = __expf(s2 - Ms);
    o0 = __expf(o0 - Mo); o1 = __expf(o1 - Mo); o2 = __expf(o2 - Mo);

    float Zs = bred(s0 + s1 + s2, false);
    float Zo = bred(o0 + o1 + o2, false);
    float rs = 1.f / Zs, ro = 1.f / Zo;

    float m0 = (float)mrow[t], m1 = (float)mrow[t + 128], m2 = (float)mrow[t + 256];
    Ss[t]       = m0 * s0 * rs + (1.f - m0) * o0 * ro;
    Ss[t + 128] = m1 * s1 * rs + (1.f - m1) * o1 * ro;
    Ss[t + 256] = m2 * s2 * rs + (1.f - m2) * o2 * ro;
}

// ---------------------------------------------------------------------------
// AV: O[bp][q][dd] = sum_k A[bp][q][k] * V[bp][k][dd]
// writes packed half2(hi,lo) into g_c2_hl[n=q][c'=dd*8+hh][sp=p]
// ---------------------------------------------------------------------------
__global__ __launch_bounds__(256) void av_kernel()
{
    __shared__ float As[16][68];
    __shared__ float Bs[16][64];

    const int bp = blockIdx.z;
    const int hh = bp >> 6, p = bp & 63;
    const int m0 = blockIdx.y * 64;
    const int tid = threadIdx.x;
    const int tx = tid & 15, ty = tid >> 4;

    const float* A = g_S + (size_t)bp * SEQ * SEQ;
    const float* V = g_feats + (size_t)4 * 8 * 64 * SEQ * HD + (size_t)bp * SEQ * HD;

    float acc[4][4] = {};

    for (int k0 = 0; k0 < SEQ; k0 += 16) {
        #pragma unroll
        for (int l = tid; l < 1024; l += 256) {
            int row = l >> 4, kkl = l & 15;
            As[kkl][row] = A[(size_t)(m0 + row) * SEQ + k0 + kkl];
        }
        #pragma unroll
        for (int l = tid; l < 1024; l += 256) {
            int kkl = l >> 6, dd = l & 63;
            Bs[kkl][dd] = V[(size_t)(k0 + kkl) * HD + dd];
        }
        __syncthreads();
        #pragma unroll
        for (int k = 0; k < 16; k++) {
            float4 a = *(const float4*)&As[k][ty * 4];
            float4 b = *(const float4*)&Bs[k][tx * 4];
            float av[4] = {a.x, a.y, a.z, a.w};
            float bv[4] = {b.x, b.y, b.z, b.w};
            #pragma unroll
            for (int i = 0; i < 4; i++)
                #pragma unroll
                for (int j = 0; j < 4; j++)
                    acc[i][j] += av[i] * bv[j];
        }
        __syncthreads();
    }

    #pragma unroll
    for (int i = 0; i < 4; i++) {
        int q = m0 + ty * 4 + i;
        #pragma unroll
        for (int j = 0; j < 4; j++) {
            int dd = tx * 4 + j;
            g_c2_hl[((size_t)q * CIN + (dd * 8 + hh)) * 64 + p] = split_h2(acc[i][j]);
        }
    }
}

// ---------------------------------------------------------------------------
extern "C" void kernel_launch(void* const* d_in, const int* in_sizes, int n_in,
                              void* d_out, int out_size)
{
    const float* inp       = (const float*)d_in[0];
    const float* attn_mask = (const float*)d_in[1];
    const int*   agent     = (const int*)  d_in[2];
    const float* w_in      = (const float*)d_in[3];
    const float* b_in      = (const float*)d_in[4];
    const float* w_out     = (const float*)d_in[5];
    const float* b_out     = (const float*)d_in[6];
    float*       out       = (float*)d_out;

    __half *wh_in, *wl_in, *wh_out, *wl_out;
    cudaGetSymbolAddress((void**)&wh_in,  g_wh_in);
    cudaGetSymbolAddress((void**)&wl_in,  g_wl_in);
    cudaGetSymbolAddress((void**)&wh_out, g_wh_out);
    cudaGetSymbolAddress((void**)&wl_out, g_wl_out);

    cudaFuncSetAttribute(conv_f16_kernel<2560, true>,
                         cudaFuncAttributeMaxDynamicSharedMemorySize, SMEM_BYTES);
    cudaFuncSetAttribute(conv_f16_kernel<512, false>,
                         cudaFuncAttributeMaxDynamicSharedMemorySize, SMEM_BYTES);

    // Pre-split weights into fp16 hi/lo (k'-permuted)
    const int n_win  = 2560 * K9;
    const int n_wout = 512 * K9;
    split_w_kernel<<<(n_win + 255) / 256, 256>>>(w_in, wh_in, wl_in, n_win);
    split_w_kernel<<<(n_wout + 255) / 256, 256>>>(w_out, wh_out, wl_out, n_wout);

    // im2col expansion of raw input
    im2col_kernel<false><<<dim3(SEQ, 8), 256>>>(inp);

    // conv_in GEMM: M = 24576 (192 blocks), N = 2560 (20 tiles), K = 4608
    conv_f16_kernel<2560, true><<<dim3(20, 192), 256, SMEM_BYTES>>>(wh_in, wl_in, b_in, nullptr);

    // Scores: 512 bp x 2 variants, 384x384, K=64
    qk_kernel<<<dim3(6, 6, 1024), 256>>>(attn_mask);

    // Dual softmax + agent blend
    softmax_kernel<<<dim3(SEQ, BP), 128>>>(agent);

    // attn @ V -> packed half2 conv2 input
    av_kernel<<<dim3(1, 6, BP), 256>>>();

    // im2col expansion of attention output (packed source)
    im2col_kernel<true><<<dim3(SEQ, 8), 256>>>(nullptr);

    // conv_out GEMM: N = 512 (4 tiles)
    conv_f16_kernel<512, false><<<dim3(4, 192), 256, SMEM_BYTES>>>(wh_out, wl_out, b_out, out);
}

// round 7
// speedup vs baseline: 3.4752x; 1.0623x over previous
#include <cuda_runtime.h>
#include <cuda_fp16.h>
#include <cstdint>

#define SEQ 384
#define CIN 512
#define HW  64
#define NH  8
#define HD  64
#define K9  (CIN * 9)        // 4608
#define BP  512              // NH * HW batch-pairs
#define NROWS (SEQ * HW)     // 24576 GEMM rows
#define SS2 (SEQ * SEQ)      // 147456

// Scratch (device globals; no runtime allocation)
__device__ uint32_t g_feats_hl[(size_t)4 * BP * SEQ * HD];  // [e][bp][n][dd] packed(hi,lo)
__device__ uint32_t g_vT[(size_t)BP * HD * SEQ];            // [bp][dd][n]   packed(hi,lo)
__device__ float    g_S[2ull * BP * SS2];                   // [v][bp][q][k] scores
__device__ uint32_t g_attn[(size_t)BP * SS2];               // blended attn, packed(hi,lo)
__device__ uint32_t g_c2_hl[(size_t)SEQ * CIN * HW];        // conv2 input, packed(hi,lo)
__device__ __half   g_Ah[(size_t)NROWS * K9];               // im2col hi plane (k' = r*512+ci)
__device__ __half   g_Al[(size_t)NROWS * K9];               // im2col lo plane
__device__ __half   g_wh_in[(size_t)2560 * K9];             // weights hi, k'-order
__device__ __half   g_wl_in[(size_t)2560 * K9];
__device__ __half   g_wh_out[(size_t)512 * K9];
__device__ __half   g_wl_out[(size_t)512 * K9];

// ---------------------------------------------------------------------------
// helpers
// ---------------------------------------------------------------------------
__device__ __forceinline__ uint32_t split_h2(float x)
{
    __half hi = __float2half_rn(x);
    __half lo = __float2half_rn(x - __half2float(hi));
    return (uint32_t)__half_as_ushort(hi) | ((uint32_t)__half_as_ushort(lo) << 16);
}

__device__ __forceinline__ void mma_f16(float c[4], const uint32_t a[4],
                                        uint32_t b0, uint32_t b1)
{
    asm volatile(
        "mma.sync.aligned.m16n8k16.row.col.f32.f16.f16.f32 "
        "{%0,%1,%2,%3}, {%4,%5,%6,%7}, {%8,%9}, {%0,%1,%2,%3};"
        : "+f"(c[0]), "+f"(c[1]), "+f"(c[2]), "+f"(c[3])
        : "r"(a[0]), "r"(a[1]), "r"(a[2]), "r"(a[3]), "r"(b0), "r"(b1));
}
__device__ __forceinline__ void ldsm4(uint32_t& r0, uint32_t& r1, uint32_t& r2,
                                      uint32_t& r3, uint32_t addr)
{
    asm volatile("ldmatrix.sync.aligned.m8n8.x4.shared.b16 {%0,%1,%2,%3}, [%4];"
                 : "=r"(r0), "=r"(r1), "=r"(r2), "=r"(r3) : "r"(addr));
}
__device__ __forceinline__ void cpa16(uint32_t dst, const void* src)
{
    asm volatile("cp.async.cg.shared.global [%0], [%1], 16;" :: "r"(dst), "l"(src));
}

// ---------------------------------------------------------------------------
// Weight split + permute to k' = r*512 + ci order
// ---------------------------------------------------------------------------
__global__ void split_w_kernel(const float* __restrict__ w,
                               __half* __restrict__ wh, __half* __restrict__ wl, int n)
{
    int i = blockIdx.x * 256 + threadIdx.x;
    if (i >= n) return;
    int co = i / K9;
    int kn = i - co * K9;
    int r = kn >> 9, ci = kn & 511;
    float x = w[(size_t)co * K9 + ci * 9 + r];
    __half hi = __float2half_rn(x);
    wh[i] = hi;
    wl[i] = __float2half_rn(x - __half2float(hi));
}

// ---------------------------------------------------------------------------
// im2col expansion into hi/lo fp16 planes, k' = r*512 + ci.
// ---------------------------------------------------------------------------
template <bool PACKED>
__global__ __launch_bounds__(256) void im2col_kernel(const float* __restrict__ srcF)
{
    __shared__ ushort th[64][72];
    __shared__ ushort tl[64][72];
    const int n   = blockIdx.x;
    const int ci0 = blockIdx.y * 64;
    const int t   = threadIdx.x;

    {
        int sp4 = (t & 15) * 4;
        int ciL = t >> 4;
        #pragma unroll
        for (int pass = 0; pass < 4; pass++) {
            int ci = pass * 16 + ciL;
            if (PACKED) {
                uint4 w = *(const uint4*)(g_c2_hl + ((size_t)n * CIN + ci0 + ci) * 64 + sp4);
                uint32_t ws[4] = {w.x, w.y, w.z, w.w};
                #pragma unroll
                for (int j = 0; j < 4; j++) {
                    th[sp4 + j][ci] = (ushort)(ws[j] & 0xFFFF);
                    tl[sp4 + j][ci] = (ushort)(ws[j] >> 16);
                }
            } else {
                float4 v = *(const float4*)(srcF + ((size_t)n * CIN + ci0 + ci) * 64 + sp4);
                float vs[4] = {v.x, v.y, v.z, v.w};
                #pragma unroll
                for (int j = 0; j < 4; j++) {
                    __half hi = __float2half_rn(vs[j]);
                    __half lo = __float2half_rn(vs[j] - __half2float(hi));
                    th[sp4 + j][ci] = __half_as_ushort(hi);
                    tl[sp4 + j][ci] = __half_as_ushort(lo);
                }
            }
        }
    }
    __syncthreads();

    const int ciQ = t & 15;
    const int rg  = t >> 4;
    #pragma unroll
    for (int si = 0; si < 4; si++) {
        int sp = si * 16 + rg;
        int yy = sp >> 3, xx = sp & 7;
        size_t obase = (size_t)(n * 64 + sp) * K9 + ci0 + ciQ * 4;
        #pragma unroll
        for (int r = 0; r < 9; r++) {
            int y = yy + r / 3 - 1, x = xx + r % 3 - 1;
            uint2 vh = make_uint2(0, 0), vl = make_uint2(0, 0);
            if ((unsigned)y < 8u && (unsigned)x < 8u) {
                int spp = y * 8 + x;
                vh = *(const uint2*)&th[spp][ciQ * 4];
                vl = *(const uint2*)&tl[spp][ciQ * 4];
            }
            *(uint2*)&g_Ah[obase + (size_t)r * 512] = vh;
            *(uint2*)&g_Al[obase + (size_t)r * 512] = vl;
        }
    }
}

// ---------------------------------------------------------------------------
// fp16x3 GEMM conv (unchanged mainloop from R6); conv_in epilogue now emits
// packed split Q/K planes and transposed packed V.
// ---------------------------------------------------------------------------
#define LDK2 20
#define STG_BYTES (4 * 128 * LDK2 * 4)
#define SMEM_BYTES (2 * STG_BYTES)

__device__ __forceinline__ void conv_fill(uint32_t base, int row0, int co0, int k0,
                                          int tid, const __half* gwh, const __half* gwl)
{
    #pragma unroll
    for (int h = 0; h < 2; h++) {
        int c = h * 256 + tid;
        int row = c >> 2, q = c & 3;
        uint32_t doff = (uint32_t)((row * LDK2 + q * 4) * 4);
        size_t aoff = (size_t)(row0 + row) * K9 + k0 + q * 8;
        size_t boff = (size_t)(co0 + row) * K9 + k0 + q * 8;
        cpa16(base + doff,         g_Ah + aoff);
        cpa16(base + 10240 + doff, g_Al + aoff);
        cpa16(base + 20480 + doff, gwh + boff);
        cpa16(base + 30720 + doff, gwl + boff);
    }
    asm volatile("cp.async.commit_group;" ::: "memory");
}

template <int CO, bool FIRST>
__global__ void __launch_bounds__(256, 2)
conv_f16_kernel(const __half* __restrict__ gwh,
                const __half* __restrict__ gwl,
                const float* __restrict__ bias,
                float* __restrict__ out)
{
    extern __shared__ uint32_t sm[];
    const uint32_t smb = (uint32_t)__cvta_generic_to_shared(sm);

    const int row0 = blockIdx.y * 128;
    const int co0  = blockIdx.x * 128;
    const int tid  = threadIdx.x;
    const int lane = tid & 31, wid = tid >> 5;
    const int rbase = (wid >> 1) * 32;
    const int cbase = (wid & 1) * 64;
    const int lg = lane >> 2, lt = lane & 3;

    const int aRow = lane & 15, aCol = (lane >> 4) * 4;
    const int bRow = ((lane >> 4) & 1) * 8 + (lane & 7);
    const int bCol = ((lane >> 3) & 1) * 4;

    float acc[2][8][4] = {};

    conv_fill(smb, row0, co0, 0, tid, gwh, gwl);

    const int NITER = K9 / 32;
    for (int it = 0; it < NITER; it++) {
        const int s = it & 1;
        asm volatile("cp.async.wait_group 0;" ::: "memory");
        __syncthreads();
        if (it + 1 < NITER)
            conv_fill(smb + (1 - s) * STG_BYTES, row0, co0, (it + 1) * 32, tid, gwh, gwl);

        const uint32_t base = smb + s * STG_BYTES;
        #pragma unroll
        for (int k16 = 0; k16 < 2; k16++) {
            const uint32_t ko = k16 * 8;
            uint32_t ah[2][4], al[2][4];
            #pragma unroll
            for (int mt = 0; mt < 2; mt++) {
                uint32_t aw = base + ((rbase + mt * 16 + aRow) * LDK2 + aCol + ko) * 4;
                ldsm4(ah[mt][0], ah[mt][1], ah[mt][2], ah[mt][3], aw);
                ldsm4(al[mt][0], al[mt][1], al[mt][2], al[mt][3], aw + 10240);
            }
            #pragma unroll
            for (int pr = 0; pr < 4; pr++) {
                uint32_t bw = base + 20480 +
                              ((cbase + pr * 16 + bRow) * LDK2 + bCol + ko) * 4;
                uint32_t bh0, bh1, bh2, bh3, bl0, bl1, bl2, bl3;
                ldsm4(bh0, bh1, bh2, bh3, bw);
                ldsm4(bl0, bl1, bl2, bl3, bw + 10240);
                #pragma unroll
                for (int mt = 0; mt < 2; mt++) {
                    mma_f16(acc[mt][2 * pr],     ah[mt], bh0, bh1);
                    mma_f16(acc[mt][2 * pr],     ah[mt], bl0, bl1);
                    mma_f16(acc[mt][2 * pr],     al[mt], bh0, bh1);
                    mma_f16(acc[mt][2 * pr + 1], ah[mt], bh2, bh3);
                    mma_f16(acc[mt][2 * pr + 1], ah[mt], bl2, bl3);
                    mma_f16(acc[mt][2 * pr + 1], al[mt], bh2, bh3);
                }
            }
        }
        __syncthreads();
    }

    // ---- epilogue ----
    #pragma unroll
    for (int mt = 0; mt < 2; mt++) {
        #pragma unroll
        for (int nt = 0; nt < 8; nt++) {
            #pragma unroll
            for (int cp = 0; cp < 4; cp++) {
                int row = row0 + rbase + mt * 16 + lg + ((cp >= 2) ? 8 : 0);
                int col = cbase + nt * 8 + lt * 2 + (cp & 1);
                int co  = co0 + col;
                float v = acc[mt][nt][cp] + bias[co];
                int n = row >> 6, sp = row & 63;
                if (FIRST) {
                    int e  = co >> 9;
                    int dd = (co >> 3) & 63;
                    int hh = co & 7;
                    int bpi = hh * 64 + sp;
                    uint32_t pv = split_h2(v);
                    if (e < 4)
                        g_feats_hl[(((size_t)e * BP + bpi) * SEQ + n) * HD + dd] = pv;
                    else
                        g_vT[((size_t)bpi * HD + dd) * SEQ + n] = pv;
                } else {
                    out[((size_t)n * CO + co) * 64 + sp] = v;
                }
            }
        }
    }
}

// ---------------------------------------------------------------------------
// QK on fp16x3 MMA: S[v][bp][q][k] = 0.125*dot(Q_{2+v},K_v) + mask.
// Tile 128x128, K=64 single-shot. smem planes (words): Qh 0, Ql 4608,
// Kh 9216, Kl 13824; row stride 36.
// ---------------------------------------------------------------------------
#define QK_SMEM (4 * 4608 * 4)   // 73728 bytes

__global__ void __launch_bounds__(256, 2)
qk_mma_kernel(const float* __restrict__ am)
{
    extern __shared__ uint32_t sm[];
    const uint32_t smb = (uint32_t)__cvta_generic_to_shared(sm);

    const int bpv = blockIdx.z, bp = bpv >> 1, v = bpv & 1, head = bp >> 6;
    const int m0 = blockIdx.y * 128, n0 = blockIdx.x * 128;
    const int tid = threadIdx.x, lane = tid & 31, wid = tid >> 5;
    const int rbase = (wid >> 1) * 32, cbase = (wid & 1) * 64;
    const int lg = lane >> 2, lt = lane & 3;
    const int aRow = lane & 15, aCol = (lane >> 4) * 4;
    const int bRow = ((lane >> 4) & 1) * 8 + (lane & 7);
    const int bCol = ((lane >> 3) & 1) * 4;

    const uint32_t* Q  = g_feats_hl + (((size_t)(2 + v) * BP + bp) * SEQ + m0) * HD;
    const uint32_t* Kp = g_feats_hl + (((size_t)v * BP + bp) * SEQ + n0) * HD;

    #pragma unroll
    for (int i = 0; i < 8; i++) {
        int lin = i * 256 + tid;
        int row = lin >> 4, q4 = lin & 15;
        uint4 wq = *(const uint4*)(Q  + (size_t)row * HD + q4 * 4);
        uint4 wk = *(const uint4*)(Kp + (size_t)row * HD + q4 * 4);
        int o = row * 36 + q4 * 2;
        *(uint2*)&sm[o]         = make_uint2(__byte_perm(wq.x, wq.y, 0x5410),
                                             __byte_perm(wq.z, wq.w, 0x5410));
        *(uint2*)&sm[4608 + o]  = make_uint2(__byte_perm(wq.x, wq.y, 0x7632),
                                             __byte_perm(wq.z, wq.w, 0x7632));
        *(uint2*)&sm[9216 + o]  = make_uint2(__byte_perm(wk.x, wk.y, 0x5410),
                                             __byte_perm(wk.z, wk.w, 0x5410));
        *(uint2*)&sm[13824 + o] = make_uint2(__byte_perm(wk.x, wk.y, 0x7632),
                                             __byte_perm(wk.z, wk.w, 0x7632));
    }
    __syncthreads();

    float acc[2][8][4] = {};
    #pragma unroll
    for (int k16 = 0; k16 < 4; k16++) {
        const int ko = k16 * 8;
        uint32_t ah[2][4], al[2][4];
        #pragma unroll
        for (int mt = 0; mt < 2; mt++) {
            uint32_t aw = smb + ((rbase + mt * 16 + aRow) * 36 + aCol + ko) * 4;
            ldsm4(ah[mt][0], ah[mt][1], ah[mt][2], ah[mt][3], aw);
            ldsm4(al[mt][0], al[mt][1], al[mt][2], al[mt][3], aw + 18432);
        }
        #pragma unroll
        for (int pr = 0; pr < 4; pr++) {
            uint32_t bw = smb + 36864 + ((cbase + pr * 16 + bRow) * 36 + bCol + ko) * 4;
            uint32_t bh0, bh1, bh2, bh3, bl0, bl1, bl2, bl3;
            ldsm4(bh0, bh1, bh2, bh3, bw);
            ldsm4(bl0, bl1, bl2, bl3, bw + 18432);
            #pragma unroll
            for (int mt = 0; mt < 2; mt++) {
                mma_f16(acc[mt][2 * pr],     ah[mt], bh0, bh1);
                mma_f16(acc[mt][2 * pr],     ah[mt], bl0, bl1);
                mma_f16(acc[mt][2 * pr],     al[mt], bh0, bh1);
                mma_f16(acc[mt][2 * pr + 1], ah[mt], bh2, bh3);
                mma_f16(acc[mt][2 * pr + 1], ah[mt], bl2, bl3);
                mma_f16(acc[mt][2 * pr + 1], al[mt], bh2, bh3);
            }
        }
    }

    float* Sout = g_S + ((size_t)v * BP + bp) * SS2;
    const float* amr = am + (size_t)head * SS2;
    #pragma unroll
    for (int mt = 0; mt < 2; mt++) {
        #pragma unroll
        for (int nt = 0; nt < 8; nt++) {
            #pragma unroll
            for (int cp = 0; cp < 4; cp++) {
                int q  = m0 + rbase + mt * 16 + lg + ((cp >= 2) ? 8 : 0);
                int kk = n0 + cbase + nt * 8 + lt * 2 + (cp & 1);
                Sout[(size_t)q * SEQ + kk] =
                    acc[mt][nt][cp] * 0.125f + amr[(size_t)q * SEQ + kk];
            }
        }
    }
}

// ---------------------------------------------------------------------------
// Dual softmax + agent-aware blend; writes packed split attn to g_attn.
// ---------------------------------------------------------------------------
__global__ __launch_bounds__(128) void softmax_kernel(const int* __restrict__ agent)
{
    __shared__ float red[128];
    const int q = blockIdx.x, bp = blockIdx.y, head = bp >> 6;
    const int t = threadIdx.x;

    const size_t base = ((size_t)bp * SEQ + q) * SEQ;
    const float* Ss = g_S + base;
    const float* So = g_S + (size_t)BP * SS2 + base;
    uint32_t* Aout = g_attn + base;
    const int* mrow = agent + ((size_t)head * SEQ + q) * SEQ;

    float s0 = Ss[t], s1 = Ss[t + 128], s2 = Ss[t + 256];
    float o0 = So[t], o1 = So[t + 128], o2 = So[t + 256];

    auto bred = [&](float val, bool ismax) -> float {
        red[t] = val; __syncthreads();
        #pragma unroll
        for (int w = 64; w > 0; w >>= 1) {
            if (t < w) red[t] = ismax ? fmaxf(red[t], red[t + w]) : (red[t] + red[t + w]);
            __syncthreads();
        }
        float r = red[0]; __syncthreads();
        return r;
    };

    float Ms = bred(fmaxf(s0, fmaxf(s1, s2)), true);
    float Mo = bred(fmaxf(o0, fmaxf(o1, o2)), true);

    s0 = __expf(s0 - Ms); s1 = __expf(s1 - Ms); s2 = __expf(s2 - Ms);
    o0 = __expf(o0 - Mo); o1 = __expf(o1 - Mo); o2 = __expf(o2 - Mo);

    float Zs = bred(s0 + s1 + s2, false);
    float Zo = bred(o0 + o1 + o2, false);
    float rs = 1.f / Zs, ro = 1.f / Zo;

    float m0 = (float)mrow[t], m1 = (float)mrow[t + 128], m2 = (float)mrow[t + 256];
    Aout[t]       = split_h2(m0 * s0 * rs + (1.f - m0) * o0 * ro);
    Aout[t + 128] = split_h2(m1 * s1 * rs + (1.f - m1) * o1 * ro);
    Aout[t + 256] = split_h2(m2 * s2 * rs + (1.f - m2) * o2 * ro);
}

// ---------------------------------------------------------------------------
// AV on fp16x3 MMA: O[bp][q][dd] = sum_k attn[q][k] * V[k][dd].
// Tile M=128 x N=64 x K=384 (6 stages of BK=64). smem words: Ah 0, Al 4608,
// Bh 9216, Bl 11520; row stride 36. Writes packed g_c2_hl.
// ---------------------------------------------------------------------------
#define AV_SMEM (13824 * 4)   // 55296 bytes

__global__ void __launch_bounds__(256, 2)
av_mma_kernel()
{
    extern __shared__ uint32_t sm[];
    const uint32_t smb = (uint32_t)__cvta_generic_to_shared(sm);

    const int bp = blockIdx.y, m0 = blockIdx.x * 128;
    const int hh = bp >> 6, p = bp & 63;
    const int tid = threadIdx.x, lane = tid & 31, wid = tid >> 5;
    const int rbase = (wid & 3) * 32, cbase = (wid >> 2) * 32;
    const int lg = lane >> 2, lt = lane & 3;
    const int aRow = lane & 15, aCol = (lane >> 4) * 4;
    const int bRow = ((lane >> 4) & 1) * 8 + (lane & 7);
    const int bCol = ((lane >> 3) & 1) * 4;

    const uint32_t* A = g_attn + (size_t)bp * SS2 + (size_t)m0 * SEQ;
    const uint32_t* V = g_vT + (size_t)bp * HD * SEQ;

    float acc[2][4][4] = {};

    for (int ks = 0; ks < 6; ks++) {
        const int k0 = ks * 64;
        __syncthreads();
        #pragma unroll
        for (int i = 0; i < 16; i++) {
            int lin = i * 256 + tid;
            int row = lin >> 5, p2 = lin & 31;
            uint2 w = *(const uint2*)(A + (size_t)row * SEQ + k0 + p2 * 2);
            sm[row * 36 + p2]        = __byte_perm(w.x, w.y, 0x5410);
            sm[4608 + row * 36 + p2] = __byte_perm(w.x, w.y, 0x7632);
        }
        #pragma unroll
        for (int i = 0; i < 8; i++) {
            int lin = i * 256 + tid;
            int row = lin >> 5, p2 = lin & 31;
            uint2 w = *(const uint2*)(V + (size_t)row * SEQ + k0 + p2 * 2);
            sm[9216 + row * 36 + p2]  = __byte_perm(w.x, w.y, 0x5410);
            sm[11520 + row * 36 + p2] = __byte_perm(w.x, w.y, 0x7632);
        }
        __syncthreads();

        #pragma unroll
        for (int k16 = 0; k16 < 4; k16++) {
            const int ko = k16 * 8;
            uint32_t ah[2][4], al[2][4];
            #pragma unroll
            for (int mt = 0; mt < 2; mt++) {
                uint32_t aw = smb + ((rbase + mt * 16 + aRow) * 36 + aCol + ko) * 4;
                ldsm4(ah[mt][0], ah[mt][1], ah[mt][2], ah[mt][3], aw);
                ldsm4(al[mt][0], al[mt][1], al[mt][2], al[mt][3], aw + 18432);
            }
            #pragma unroll
            for (int pr = 0; pr < 2; pr++) {
                uint32_t bw = smb + 36864 + ((cbase + pr * 16 + bRow) * 36 + bCol + ko) * 4;
                uint32_t bh0, bh1, bh2, bh3, bl0, bl1, bl2, bl3;
                ldsm4(bh0, bh1, bh2, bh3, bw);
                ldsm4(bl0, bl1, bl2, bl3, bw + 9216);
                #pragma unroll
                for (int mt = 0; mt < 2; mt++) {
                    mma_f16(acc[mt][2 * pr],     ah[mt], bh0, bh1);
                    mma_f16(acc[mt][2 * pr],     ah[mt], bl0, bl1);
                    mma_f16(acc[mt][2 * pr],     al[mt], bh0, bh1);
                    mma_f16(acc[mt][2 * pr + 1], ah[mt], bh2, bh3);
                    mma_f16(acc[mt][2 * pr + 1], ah[mt], bl2, bl3);
                    mma_f16(acc[mt][2 * pr + 1], al[mt], bh2, bh3);
                }
            }
        }
    }

    #pragma unroll
    for (int mt = 0; mt < 2; mt++) {
        #pragma unroll
        for (int nt = 0; nt < 4; nt++) {
            #pragma unroll
            for (int cp = 0; cp < 4; cp++) {
                int q  = m0 + rbase + mt * 16 + lg + ((cp >= 2) ? 8 : 0);
                int dd = cbase + nt * 8 + lt * 2 + (cp & 1);
                g_c2_hl[((size_t)q * CIN + (dd * 8 + hh)) * 64 + p] =
                    split_h2(acc[mt][nt][cp]);
            }
        }
    }
}

// ---------------------------------------------------------------------------
extern "C" void kernel_launch(void* const* d_in, const int* in_sizes, int n_in,
                              void* d_out, int out_size)
{
    const float* inp       = (const float*)d_in[0];
    const float* attn_mask = (const float*)d_in[1];
    const int*   agent     = (const int*)  d_in[2];
    const float* w_in      = (const float*)d_in[3];
    const float* b_in      = (const float*)d_in[4];
    const float* w_out     = (const float*)d_in[5];
    const float* b_out     = (const float*)d_in[6];
    float*       out       = (float*)d_out;

    __half *wh_in, *wl_in, *wh_out, *wl_out;
    cudaGetSymbolAddress((void**)&wh_in,  g_wh_in);
    cudaGetSymbolAddress((void**)&wl_in,  g_wl_in);
    cudaGetSymbolAddress((void**)&wh_out, g_wh_out);
    cudaGetSymbolAddress((void**)&wl_out, g_wl_out);

    cudaFuncSetAttribute(conv_f16_kernel<2560, true>,
                         cudaFuncAttributeMaxDynamicSharedMemorySize, SMEM_BYTES);
    cudaFuncSetAttribute(conv_f16_kernel<512, false>,
                         cudaFuncAttributeMaxDynamicSharedMemorySize, SMEM_BYTES);
    cudaFuncSetAttribute(qk_mma_kernel,
                         cudaFuncAttributeMaxDynamicSharedMemorySize, QK_SMEM);
    cudaFuncSetAttribute(av_mma_kernel,
                         cudaFuncAttributeMaxDynamicSharedMemorySize, AV_SMEM);

    const int n_win  = 2560 * K9;
    const int n_wout = 512 * K9;
    split_w_kernel<<<(n_win + 255) / 256, 256>>>(w_in, wh_in, wl_in, n_win);
    split_w_kernel<<<(n_wout + 255) / 256, 256>>>(w_out, wh_out, wl_out, n_wout);

    // im2col expansion of raw input
    im2col_kernel<false><<<dim3(SEQ, 8), 256>>>(inp);

    // conv_in GEMM: emits packed Q/K planes + transposed V
    conv_f16_kernel<2560, true><<<dim3(20, 192), 256, SMEM_BYTES>>>(wh_in, wl_in, b_in, nullptr);

    // Scores on tensor cores: 1024 (bp,v) x 3x3 tiles of 128
    qk_mma_kernel<<<dim3(3, 3, 1024), 256, QK_SMEM>>>(attn_mask);

    // Dual softmax + agent blend -> packed attn
    softmax_kernel<<<dim3(SEQ, BP), 128>>>(agent);

    // attn @ V on tensor cores -> packed conv2 input
    av_mma_kernel<<<dim3(3, BP), 256, AV_SMEM>>>();

    // im2col expansion of attention output (packed source)
    im2col_kernel<true><<<dim3(SEQ, 8), 256>>>(nullptr);

    // conv_out GEMM
    conv_f16_kernel<512, false><<<dim3(4, 192), 256, SMEM_BYTES>>>(wh_out, wl_out, b_out, out);
}